// round 10
// baseline (speedup 1.0000x reference)
#include <cuda_runtime.h>
#include <math.h>

#define BB 4
#define NN 4096
#define KK 16
#define K17 17
#define EPSF 1e-12f
#define TPB 1024
#define BLKQ 128              // query slots per block
#define BPB 37                // blocks per batch -> grid = 4*37 = 148 = SM count
#define SEGS 8
#define SEGN (NN / SEGS)      // 512
#define CHUNK 32
#define CCAP 8
#define NSLOT 6               // merge-tree list slots
#define BIGF 3.4e38f

// scratch: kappa values for [pass][batch][point]; pass 0 = ori, pass 1 = adv
__device__ float g_kappa[2][BB][NN];

// ---- dynamic smem layout (bytes) ----
#define OFF_TILE 0                                   // float4 [NN]            65536
#define OFF_PD   (OFF_TILE + NN * 16)                // float [NSLOT][BLKQ][K17] 52224
#define OFF_PI   (OFF_PD + NSLOT * BLKQ * K17 * 4)   // u16   [NSLOT][BLKQ][K17] 26112
#define OFF_AMD  (OFF_PI + NSLOT * BLKQ * K17 * 2)   // float [SEGS*BLKQ]        4096
#define OFF_AMI  (OFF_AMD + SEGS * BLKQ * 4)         // int   [SEGS*BLKQ]        4096
#define OFF_RS   (OFF_AMI + SEGS * BLKQ * 4)         // float [SEGS*BLKQ]        4096
#define SMEM_TOTAL (OFF_RS + SEGS * BLKQ * 4)        // = 156160 (~152.5 KB)

__device__ __forceinline__ void insert17(float* bd, int* bi, float d, int i)
{
#pragma unroll
    for (int t = 0; t < K17; ++t) {
        if (d < bd[t]) {
            float td = bd[t]; bd[t] = d; d = td;
            int   ti = bi[t]; bi[t] = i; i = ti;
        }
    }
}

__device__ __forceinline__ void load_tile(float4* tile, const float* pc, int tid)
{
    for (int j = tid; j < NN; j += TPB) {
        float x = pc[3 * j + 0];
        float y = pc[3 * j + 1];
        float z = pc[3 * j + 2];
        tile[j] = make_float4(x, y, z, x * x + y * y + z * z);
    }
}

// Round-3 distance expression, verbatim
__device__ __forceinline__ float dref(float4 p, float ax, float ay, float az, float na)
{
    float dot = fmaf(az, p.z, fmaf(ay, p.y, ax * p.x));
    return fmaf(-2.0f, dot, na + p.w);
}

// Per-segment provable bound: 5th-smallest of 64 stride-8 samples.
// >=5 candidates/segment are <= s4 => >=40 total <= max_seg(s4) = R => d_(17) <= R.
__device__ __forceinline__ float sample_bound(
    const float4* __restrict__ tile, int segbase,
    float ax, float ay, float az, float na)
{
    float s0 = BIGF, s1 = BIGF, s2 = BIGF, s3 = BIGF, s4 = BIGF;
#pragma unroll 4
    for (int t = 0; t < 64; ++t) {
        float c = dref(tile[segbase + (t << 3)], ax, ay, az, na);
        float m;
        m = fminf(s0, c); c = fmaxf(s0, c); s0 = m;
        m = fminf(s1, c); c = fmaxf(s1, c); s1 = m;
        m = fminf(s2, c); c = fmaxf(s2, c); s2 = m;
        m = fminf(s3, c); c = fmaxf(s3, c); s3 = m;
        m = fminf(s4, c); c = fmaxf(s4, c); s4 = m;
    }
    return s4;
}

// Chunked filtered exact scan (bit-identical selection; see Round 8/9 notes).
template <bool DO_ARGMIN>
__device__ __forceinline__ void scan_seg(
    const float4* __restrict__ tile, int segbase, float R,
    float ax, float ay, float az, float na,
    float bx, float by, float bz, float nb,
    float* bd, int* bi, float* dmin_out, int* jmin_out)
{
    float worst = bd[K17 - 1];
    float lim = fminf(R, worst);
    float dmin = BIGF; int jmin = 0;
    for (int c0 = 0; c0 < SEGN; c0 += CHUNK) {
        float bufd[CCAP];
        int   bufj[CCAP];
        int c = 0;
#pragma unroll 4
        for (int j = c0; j < c0 + CHUNK; ++j) {
            float4 p = tile[segbase + j];
            float d = dref(p, ax, ay, az, na);
            if (DO_ARGMIN) {
                float d2 = dref(p, bx, by, bz, nb);
                if (d2 < dmin) { dmin = d2; jmin = segbase + j; }
            }
            if (d <= lim) {
                if (c < CCAP) { bufd[c] = d; bufj[c] = segbase + j; ++c; }
                else { insert17(bd, bi, d, segbase + j); worst = bd[K17 - 1]; }
            }
        }
        for (int t = 0; t < c; ++t) {
            float d = bufd[t];
            if (d < worst) {
                insert17(bd, bi, d, bufj[t]);
                worst = bd[K17 - 1];
            }
        }
        lim = fminf(R, worst);
    }
    if (DO_ARGMIN) { *dmin_out = dmin; *jmin_out = jmin; }
}

__device__ __forceinline__ void publish_list(float* pd, unsigned short* pi,
                                             int slot, int ql,
                                             const float* bd, const int* bi)
{
    float* qd = pd + (slot * BLKQ + ql) * K17;
    unsigned short* qi = pi + (slot * BLKQ + ql) * K17;
#pragma unroll
    for (int t = 0; t < K17; ++t) { qd[t] = bd[t]; qi[t] = (unsigned short)bi[t]; }
}

// absorb one sorted list into (bd,bi); incoming indices are strictly higher
// than all resident ones, and resident wins strict-'<' ties => lowest-index
// tie-break preserved (matches sequential merge and jax).
__device__ __forceinline__ void absorb_list(const float* pd, const unsigned short* pi,
                                            int slot, int ql, float* bd, int* bi)
{
    const float* qd = pd + (slot * BLKQ + ql) * K17;
    const unsigned short* qi = pi + (slot * BLKQ + ql) * K17;
    float worst = bd[K17 - 1];
    for (int t = 0; t < K17; ++t) {
        float d = qd[t];
        if (d >= worst) break;
        insert17(bd, bi, d, (int)qi[t]);
        worst = bd[K17 - 1];
    }
}

__device__ __forceinline__ float kappa_from_topk(const float4* tile,
                                                 float ax, float ay, float az,
                                                 float nx, float ny, float nz,
                                                 const int* bi)
{
    float s = 0.0f;
#pragma unroll
    for (int t = 1; t < K17; ++t) {     // drop entry 0 (self / nearest)
        float4 p = tile[bi[t]];
        float vx = p.x - ax, vy = p.y - ay, vz = p.z - az;
        float nv = sqrtf(vx * vx + vy * vy + vz * vz);
        float inv = 1.0f / (nv + EPSF);
        s += fabsf((vx * nx + vy * ny + vz * nz) * inv);
    }
    return s * (1.0f / KK);
}

// ---------------------------------------------------------------------------
// fused kernel: ori top-17 + adv argmin on the ori tile, then adv top-17.
// 8 segment-threads per query; 3-step tree merge.
// ---------------------------------------------------------------------------
__global__ __launch_bounds__(TPB, 1) void kappa_all_kernel(
    const float* __restrict__ ori, const float* __restrict__ adv,
    const float* __restrict__ nrm)
{
    extern __shared__ char smem[];
    float4* tile = (float4*)(smem + OFF_TILE);
    float*  pd   = (float*)(smem + OFF_PD);
    unsigned short* pi = (unsigned short*)(smem + OFF_PI);
    float*  amd  = (float*)(smem + OFF_AMD);
    int*    ami  = (int*)(smem + OFF_AMI);
    float*  rs   = (float*)(smem + OFF_RS);

    const int tid = threadIdx.x;
    const int ql  = tid % BLKQ;
    const int seg = tid / BLKQ;            // 0..7
    const int segbase = seg * SEGN;
    const int b   = blockIdx.x / BPB;
    const int blk = blockIdx.x % BPB;
    const int q0    = (blk * NN) / BPB;
    const int q1    = ((blk + 1) * NN) / BPB;
    const int count = q1 - q0;             // 110 or 111
    const int q   = q0 + ql;
    const int qe  = (ql < count) ? q : q0;
    const bool active = (ql < count);

    const float* pco = ori + (size_t)b * NN * 3;
    const float* pca = adv + (size_t)b * NN * 3;
    const float* nr  = nrm + (size_t)b * NN * 3;

    const float ax = pco[3 * qe + 0];
    const float ay = pco[3 * qe + 1];
    const float az = pco[3 * qe + 2];
    const float na = ax * ax + ay * ay + az * az;
    const float bx = pca[3 * qe + 0];
    const float by = pca[3 * qe + 1];
    const float bz = pca[3 * qe + 2];
    const float nb = bx * bx + by * by + bz * bz;

    float bd[K17]; int bi[K17];
    float nx = 0.f, ny = 0.f, nz = 0.f;

    // ===================== phase A: ori tile =====================
    load_tile(tile, pco, tid);
    __syncthreads();

    rs[seg * BLKQ + ql] = sample_bound(tile, segbase, ax, ay, az, na);
    __syncthreads();
    {
        float r01 = fmaxf(rs[0 * BLKQ + ql], rs[1 * BLKQ + ql]);
        float r23 = fmaxf(rs[2 * BLKQ + ql], rs[3 * BLKQ + ql]);
        float r45 = fmaxf(rs[4 * BLKQ + ql], rs[5 * BLKQ + ql]);
        float r67 = fmaxf(rs[6 * BLKQ + ql], rs[7 * BLKQ + ql]);
        float R = fmaxf(fmaxf(r01, r23), fmaxf(r45, r67));

#pragma unroll
        for (int t = 0; t < K17; ++t) { bd[t] = BIGF; bi[t] = 0; }

        float dmin; int jmin;
        scan_seg<true>(tile, segbase, R, ax, ay, az, na, bx, by, bz, nb,
                       bd, bi, &dmin, &jmin);
        amd[seg * BLKQ + ql] = dmin;
        ami[seg * BLKQ + ql] = jmin;
    }

    // --- merge tree: 0<-1, 2<-3, 4<-5, 6<-7 ; 0<-2, 4<-6 ; 0<-4 ---
    if (seg & 1) publish_list(pd, pi, seg >> 1, ql, bd, bi);      // slots 0..3
    __syncthreads();
    if (!(seg & 1)) absorb_list(pd, pi, seg >> 1, ql, bd, bi);
    if ((seg & 3) == 2) publish_list(pd, pi, 4 + (seg >> 2), ql, bd, bi); // slots 4,5
    __syncthreads();
    if ((seg & 3) == 0) absorb_list(pd, pi, 4 + (seg >> 2), ql, bd, bi);  // segs 0,4
    if (seg == 4) publish_list(pd, pi, 0, ql, bd, bi);            // slot 0 (free)
    __syncthreads();

    if (seg == 0) {
        absorb_list(pd, pi, 0, ql, bd, bi);
        if (active) {
            float onx = nr[3 * q + 0], ony = nr[3 * q + 1], onz = nr[3 * q + 2];
            g_kappa[0][b][q] = kappa_from_topk(tile, ax, ay, az, onx, ony, onz, bi);
        }
        // nearest-ori normal for the adv query (first-min across segs)
        float best = BIGF; int jm = 0;
#pragma unroll
        for (int s = 0; s < SEGS; ++s) {
            float d = amd[s * BLKQ + ql];
            if (d < best) { best = d; jm = ami[s * BLKQ + ql]; }
        }
        nx = nr[3 * jm + 0]; ny = nr[3 * jm + 1]; nz = nr[3 * jm + 2];
    }
    __syncthreads();   // everyone done reading ori tile

    // ===================== phase B: adv tile =====================
    load_tile(tile, pca, tid);
    __syncthreads();

    rs[seg * BLKQ + ql] = sample_bound(tile, segbase, bx, by, bz, nb);
    __syncthreads();
    {
        float r01 = fmaxf(rs[0 * BLKQ + ql], rs[1 * BLKQ + ql]);
        float r23 = fmaxf(rs[2 * BLKQ + ql], rs[3 * BLKQ + ql]);
        float r45 = fmaxf(rs[4 * BLKQ + ql], rs[5 * BLKQ + ql]);
        float r67 = fmaxf(rs[6 * BLKQ + ql], rs[7 * BLKQ + ql]);
        float R = fmaxf(fmaxf(r01, r23), fmaxf(r45, r67));

#pragma unroll
        for (int t = 0; t < K17; ++t) { bd[t] = BIGF; bi[t] = 0; }

        float dmin; int jmin;
        scan_seg<false>(tile, segbase, R, bx, by, bz, nb, 0.f, 0.f, 0.f, 0.f,
                        bd, bi, &dmin, &jmin);
    }

    if (seg & 1) publish_list(pd, pi, seg >> 1, ql, bd, bi);
    __syncthreads();
    if (!(seg & 1)) absorb_list(pd, pi, seg >> 1, ql, bd, bi);
    if ((seg & 3) == 2) publish_list(pd, pi, 4 + (seg >> 2), ql, bd, bi);
    __syncthreads();
    if ((seg & 3) == 0) absorb_list(pd, pi, 4 + (seg >> 2), ql, bd, bi);
    if (seg == 4) publish_list(pd, pi, 0, ql, bd, bi);
    __syncthreads();

    if (seg == 0 && active) {
        absorb_list(pd, pi, 0, ql, bd, bi);
        g_kappa[1][b][q] = kappa_from_topk(tile, bx, by, bz, nx, ny, nz, bi);
    }
}

// ---------------------------------------------------------------------------
// parallel reduce: 8 groups of 128 threads, one per (pass, batch)
// ---------------------------------------------------------------------------
__global__ __launch_bounds__(1024) void reduce_kernel(float* __restrict__ out)
{
    __shared__ double red[1024];
    __shared__ double s_std[8];
    const int tid = threadIdx.x;
    const int g = tid >> 7;
    const int l = tid & 127;
    const int p = g >> 2;
    const int b = g & 3;

    double s = 0.0;
    for (int i = l; i < NN; i += 128) s += (double)g_kappa[p][b][i];
    red[tid] = s;
    __syncthreads();
    for (int st = 64; st > 0; st >>= 1) {
        if (l < st) red[tid] += red[tid + st];
        __syncthreads();
    }
    double mean = red[g << 7] / (double)NN;
    __syncthreads();

    double s2 = 0.0;
    for (int i = l; i < NN; i += 128) {
        double dv = (double)g_kappa[p][b][i] - mean;
        s2 += dv * dv;
    }
    red[tid] = s2;
    __syncthreads();
    for (int st = 64; st > 0; st >>= 1) {
        if (l < st) red[tid] += red[tid + st];
        __syncthreads();
    }
    if (l == 0) s_std[g] = sqrt(red[tid] / (double)(NN - 1));
    __syncthreads();

    if (tid == 0) {
        double acc = 0.0;
        for (int bb = 0; bb < BB; ++bb) acc += fabs(s_std[4 + bb] - s_std[bb]);
        out[0] = (float)(acc / (double)BB);
    }
}

// ---------------------------------------------------------------------------
extern "C" void kernel_launch(void* const* d_in, const int* in_sizes, int n_in,
                              void* d_out, int out_size)
{
    const float* ori = (const float*)d_in[0];
    const float* adv = (const float*)d_in[1];
    const float* nrm = (const float*)d_in[2];
    float* out = (float*)d_out;

    cudaFuncSetAttribute(kappa_all_kernel,
                         cudaFuncAttributeMaxDynamicSharedMemorySize, SMEM_TOTAL);

    kappa_all_kernel<<<BB * BPB, TPB, SMEM_TOTAL>>>(ori, adv, nrm);
    reduce_kernel<<<1, 1024>>>(out);
}

// round 11
// speedup vs baseline: 1.5237x; 1.5237x over previous
#include <cuda_runtime.h>
#include <math.h>

#define BB 4
#define NN 4096
#define KK 16
#define K17 17
#define EPSF 1e-12f
#define TPB 512
#define BLKQ 128              // query slots per block
#define BPB 37                // blocks per batch -> grid = 4*37 = 148 = SM count
#define SEGS 4
#define SEGN (NN / SEGS)      // 1024
#define CHUNK 64
#define CCAP 16
#define BIGF 3.4e38f

// scratch: kappa values for [pass][batch][point]; pass 0 = ori, pass 1 = adv
__device__ float g_kappa[2][BB][NN];

// ---- dynamic smem layout (bytes) ----
#define OFF_TILE 0                                      // float4 [NN]           65536
#define OFF_PD   (OFF_TILE + NN * 16)                   // float [3][BLKQ][K17]  26112
#define OFF_PI   (OFF_PD + (SEGS - 1) * BLKQ * K17 * 4) // u16   [3][BLKQ][K17]  13056
#define OFF_AMD  (OFF_PI + (SEGS - 1) * BLKQ * K17 * 2) // float [SEGS*BLKQ]      2048
#define OFF_AMI  (OFF_AMD + SEGS * BLKQ * 4)            // int   [SEGS*BLKQ]      2048
#define OFF_RS   (OFF_AMI + SEGS * BLKQ * 4)            // float [SEGS*BLKQ]      2048
#define SMEM_TOTAL (OFF_RS + SEGS * BLKQ * 4)           // = 110848 (~108 KB)

__device__ __forceinline__ void insert17(float* bd, int* bi, float d, int i)
{
#pragma unroll
    for (int t = 0; t < K17; ++t) {
        if (d < bd[t]) {
            float td = bd[t]; bd[t] = d; d = td;
            int   ti = bi[t]; bi[t] = i; i = ti;
        }
    }
}

__device__ __forceinline__ void load_tile(float4* tile, const float* pc, int tid)
{
    for (int j = tid; j < NN; j += TPB) {
        float x = pc[3 * j + 0];
        float y = pc[3 * j + 1];
        float z = pc[3 * j + 2];
        tile[j] = make_float4(x, y, z, x * x + y * y + z * z);
    }
}

// Round-3 distance expression, verbatim
__device__ __forceinline__ float dref(float4 p, float ax, float ay, float az, float na)
{
    float dot = fmaf(az, p.z, fmaf(ay, p.y, ax * p.x));
    return fmaf(-2.0f, dot, na + p.w);
}

// Per-segment provable bound via TWO independent 5-min networks (ILP x2).
// Half A: >=5 candidates of this segment are <= s4A. Same for half B.
// min(s4A, s4B) therefore still has >=5 segment candidates <= it (from the
// winning half), and is tighter than either half alone. Across 4 segments:
// >=20 candidates <= R = max_seg(bound) => d_(17) <= R. Filter-safe always.
__device__ __forceinline__ float sample_bound(
    const float4* __restrict__ tile, int segbase,
    float ax, float ay, float az, float na)
{
    float a0 = BIGF, a1 = BIGF, a2 = BIGF, a3 = BIGF, a4 = BIGF;
    float b0 = BIGF, b1 = BIGF, b2 = BIGF, b3 = BIGF, b4 = BIGF;
#pragma unroll 4
    for (int t = 0; t < 64; ++t) {
        float ca = dref(tile[segbase + (t << 4)], ax, ay, az, na);
        float cb = dref(tile[segbase + (t << 4) + 8], ax, ay, az, na);
        float m;
        m = fminf(a0, ca); ca = fmaxf(a0, ca); a0 = m;
        m = fminf(b0, cb); cb = fmaxf(b0, cb); b0 = m;
        m = fminf(a1, ca); ca = fmaxf(a1, ca); a1 = m;
        m = fminf(b1, cb); cb = fmaxf(b1, cb); b1 = m;
        m = fminf(a2, ca); ca = fmaxf(a2, ca); a2 = m;
        m = fminf(b2, cb); cb = fmaxf(b2, cb); b2 = m;
        m = fminf(a3, ca); ca = fmaxf(a3, ca); a3 = m;
        m = fminf(b3, cb); cb = fmaxf(b3, cb); b3 = m;
        m = fminf(a4, ca); a4 = m;
        m = fminf(b4, cb); b4 = m;
    }
    return fminf(a4, b4);
}

// Chunked filtered exact scan (bit-identical selection; see Round 8/9 notes).
// unroll 8: eight independent LDS+dref chains in flight per warp.
template <bool DO_ARGMIN>
__device__ __forceinline__ void scan_seg(
    const float4* __restrict__ tile, int segbase, float R,
    float ax, float ay, float az, float na,
    float bx, float by, float bz, float nb,
    float* bd, int* bi, float* dmin_out, int* jmin_out)
{
    float worst = bd[K17 - 1];
    float lim = fminf(R, worst);
    float dmin = BIGF; int jmin = 0;
    for (int c0 = 0; c0 < SEGN; c0 += CHUNK) {
        float bufd[CCAP];
        int   bufj[CCAP];
        int c = 0;
#pragma unroll 8
        for (int j = c0; j < c0 + CHUNK; ++j) {
            float4 p = tile[segbase + j];
            float d = dref(p, ax, ay, az, na);
            if (DO_ARGMIN) {
                float d2 = dref(p, bx, by, bz, nb);
                if (d2 < dmin) { dmin = d2; jmin = segbase + j; }
            }
            if (d <= lim) {
                if (c < CCAP) { bufd[c] = d; bufj[c] = segbase + j; ++c; }
                else { insert17(bd, bi, d, segbase + j); worst = bd[K17 - 1]; }
            }
        }
        for (int t = 0; t < c; ++t) {
            float d = bufd[t];
            if (d < worst) {
                insert17(bd, bi, d, bufj[t]);
                worst = bd[K17 - 1];
            }
        }
        lim = fminf(R, worst);
    }
    if (DO_ARGMIN) { *dmin_out = dmin; *jmin_out = jmin; }
}

// merge 3 other partial lists into (bd,bi), lists sorted ascending
__device__ __forceinline__ void merge_partials(const float* pd, const unsigned short* pi,
                                               int ql, float* bd, int* bi)
{
    float worst = bd[K17 - 1];
#pragma unroll
    for (int s = 0; s < SEGS - 1; ++s) {
        const float* qd = pd + (s * BLKQ + ql) * K17;
        const unsigned short* qi = pi + (s * BLKQ + ql) * K17;
        for (int t = 0; t < K17; ++t) {
            float d = qd[t];
            if (d >= worst) break;
            insert17(bd, bi, d, (int)qi[t]);
            worst = bd[K17 - 1];
        }
    }
}

__device__ __forceinline__ float kappa_from_topk(const float4* tile,
                                                 float ax, float ay, float az,
                                                 float nx, float ny, float nz,
                                                 const int* bi)
{
    float s = 0.0f;
#pragma unroll
    for (int t = 1; t < K17; ++t) {     // drop entry 0 (self / nearest)
        float4 p = tile[bi[t]];
        float vx = p.x - ax, vy = p.y - ay, vz = p.z - az;
        float nv = sqrtf(vx * vx + vy * vy + vz * vz);
        float inv = 1.0f / (nv + EPSF);
        s += fabsf((vx * nx + vy * ny + vz * nz) * inv);
    }
    return s * (1.0f / KK);
}

__device__ __forceinline__ void publish_partials(float* pd, unsigned short* pi,
                                                 int seg, int ql,
                                                 const float* bd, const int* bi)
{
    float* qd = pd + ((seg - 1) * BLKQ + ql) * K17;
    unsigned short* qi = pi + ((seg - 1) * BLKQ + ql) * K17;
#pragma unroll
    for (int t = 0; t < K17; ++t) { qd[t] = bd[t]; qi[t] = (unsigned short)bi[t]; }
}

// ---------------------------------------------------------------------------
// fused kernel: ori top-17 + adv argmin on the ori tile, then adv top-17.
// Grid = BB * BPB = 148 blocks; block i of a batch covers queries
// [i*NN/BPB, (i+1)*NN/BPB)  (110 or 111 queries; slots up to BLKQ=128).
// ---------------------------------------------------------------------------
__global__ __launch_bounds__(TPB, 1) void kappa_all_kernel(
    const float* __restrict__ ori, const float* __restrict__ adv,
    const float* __restrict__ nrm)
{
    extern __shared__ char smem[];
    float4* tile = (float4*)(smem + OFF_TILE);
    float*  pd   = (float*)(smem + OFF_PD);
    unsigned short* pi = (unsigned short*)(smem + OFF_PI);
    float*  amd  = (float*)(smem + OFF_AMD);
    int*    ami  = (int*)(smem + OFF_AMI);
    float*  rs   = (float*)(smem + OFF_RS);

    const int tid = threadIdx.x;
    const int ql  = tid % BLKQ;
    const int seg = tid / BLKQ;
    const int segbase = seg * SEGN;
    const int b   = blockIdx.x / BPB;
    const int blk = blockIdx.x % BPB;
    const int q0    = (blk * NN) / BPB;
    const int q1    = ((blk + 1) * NN) / BPB;
    const int count = q1 - q0;                 // 110 or 111
    const int q   = q0 + ql;
    const int qe  = (ql < count) ? q : q0;     // clamped for loads
    const bool active = (ql < count);

    const float* pco = ori + (size_t)b * NN * 3;
    const float* pca = adv + (size_t)b * NN * 3;
    const float* nr  = nrm + (size_t)b * NN * 3;

    const float ax = pco[3 * qe + 0];
    const float ay = pco[3 * qe + 1];
    const float az = pco[3 * qe + 2];
    const float na = ax * ax + ay * ay + az * az;
    const float bx = pca[3 * qe + 0];
    const float by = pca[3 * qe + 1];
    const float bz = pca[3 * qe + 2];
    const float nb = bx * bx + by * by + bz * bz;

    // ===================== phase A: ori tile =====================
    load_tile(tile, pco, tid);
    __syncthreads();

    rs[seg * BLKQ + ql] = sample_bound(tile, segbase, ax, ay, az, na);
    __syncthreads();
    float R = fmaxf(fmaxf(rs[0 * BLKQ + ql], rs[1 * BLKQ + ql]),
                    fmaxf(rs[2 * BLKQ + ql], rs[3 * BLKQ + ql]));

    float bd[K17]; int bi[K17];
#pragma unroll
    for (int t = 0; t < K17; ++t) { bd[t] = BIGF; bi[t] = 0; }

    float dmin; int jmin;
    scan_seg<true>(tile, segbase, R, ax, ay, az, na, bx, by, bz, nb,
                   bd, bi, &dmin, &jmin);

    amd[seg * BLKQ + ql] = dmin;
    ami[seg * BLKQ + ql] = jmin;
    if (seg != 0) publish_partials(pd, pi, seg, ql, bd, bi);
    __syncthreads();

    float nx = 0.f, ny = 0.f, nz = 0.f;
    if (seg == 0) {
        merge_partials(pd, pi, ql, bd, bi);
        if (active) {
            float onx = nr[3 * q + 0], ony = nr[3 * q + 1], onz = nr[3 * q + 2];
            g_kappa[0][b][q] = kappa_from_topk(tile, ax, ay, az, onx, ony, onz, bi);
        }
        // gather nearest-ori normal for the adv query (first-min across segs)
        float best = BIGF; int jm = 0;
#pragma unroll
        for (int s = 0; s < SEGS; ++s) {
            float d = amd[s * BLKQ + ql];
            if (d < best) { best = d; jm = ami[s * BLKQ + ql]; }
        }
        nx = nr[3 * jm + 0]; ny = nr[3 * jm + 1]; nz = nr[3 * jm + 2];
    }
    __syncthreads();   // everyone done reading ori tile

    // ===================== phase B: adv tile =====================
    load_tile(tile, pca, tid);
    __syncthreads();

    rs[seg * BLKQ + ql] = sample_bound(tile, segbase, bx, by, bz, nb);
    __syncthreads();
    R = fmaxf(fmaxf(rs[0 * BLKQ + ql], rs[1 * BLKQ + ql]),
              fmaxf(rs[2 * BLKQ + ql], rs[3 * BLKQ + ql]));

#pragma unroll
    for (int t = 0; t < K17; ++t) { bd[t] = BIGF; bi[t] = 0; }

    scan_seg<false>(tile, segbase, R, bx, by, bz, nb, 0.f, 0.f, 0.f, 0.f,
                    bd, bi, &dmin, &jmin);

    if (seg != 0) publish_partials(pd, pi, seg, ql, bd, bi);
    __syncthreads();

    if (seg == 0 && active) {
        merge_partials(pd, pi, ql, bd, bi);
        g_kappa[1][b][q] = kappa_from_topk(tile, bx, by, bz, nx, ny, nz, bi);
    }
}

// ---------------------------------------------------------------------------
// parallel reduce: 8 groups of 128 threads, one per (pass, batch)
// ---------------------------------------------------------------------------
__global__ __launch_bounds__(1024) void reduce_kernel(float* __restrict__ out)
{
    __shared__ double red[1024];
    __shared__ double s_std[8];
    const int tid = threadIdx.x;
    const int g = tid >> 7;
    const int l = tid & 127;
    const int p = g >> 2;
    const int b = g & 3;

    double s = 0.0;
    for (int i = l; i < NN; i += 128) s += (double)g_kappa[p][b][i];
    red[tid] = s;
    __syncthreads();
    for (int st = 64; st > 0; st >>= 1) {
        if (l < st) red[tid] += red[tid + st];
        __syncthreads();
    }
    double mean = red[g << 7] / (double)NN;
    __syncthreads();

    double s2 = 0.0;
    for (int i = l; i < NN; i += 128) {
        double dv = (double)g_kappa[p][b][i] - mean;
        s2 += dv * dv;
    }
    red[tid] = s2;
    __syncthreads();
    for (int st = 64; st > 0; st >>= 1) {
        if (l < st) red[tid] += red[tid + st];
        __syncthreads();
    }
    if (l == 0) s_std[g] = sqrt(red[tid] / (double)(NN - 1));
    __syncthreads();

    if (tid == 0) {
        double acc = 0.0;
        for (int bb = 0; bb < BB; ++bb) acc += fabs(s_std[4 + bb] - s_std[bb]);
        out[0] = (float)(acc / (double)BB);
    }
}

// ---------------------------------------------------------------------------
extern "C" void kernel_launch(void* const* d_in, const int* in_sizes, int n_in,
                              void* d_out, int out_size)
{
    const float* ori = (const float*)d_in[0];
    const float* adv = (const float*)d_in[1];
    const float* nrm = (const float*)d_in[2];
    float* out = (float*)d_out;

    cudaFuncSetAttribute(kappa_all_kernel,
                         cudaFuncAttributeMaxDynamicSharedMemorySize, SMEM_TOTAL);

    kappa_all_kernel<<<BB * BPB, TPB, SMEM_TOTAL>>>(ori, adv, nrm);
    reduce_kernel<<<1, 1024>>>(out);
}

// round 12
// speedup vs baseline: 1.6033x; 1.0523x over previous
#include <cuda_runtime.h>
#include <math.h>

#define BB 4
#define NN 4096
#define KK 16
#define K17 17
#define EPSF 1e-12f
#define TPB 512
#define BLKQ 128              // query slots per block
#define BPB 37                // blocks per batch -> grid = 4*37 = 148 = SM count
#define SEGS 4
#define SEGN (NN / SEGS)      // 1024
#define CHUNK 64
#define CCAP 16
#define BIGF 3.4e38f

// scratch: kappa values for [pass][batch][point]; pass 0 = ori, pass 1 = adv
__device__ float g_kappa[2][BB][NN];

// ---- dynamic smem layout (bytes) ----
#define OFF_TILE 0                                      // float4 [NN]           65536
#define OFF_PD   (OFF_TILE + NN * 16)                   // float [3][BLKQ][K17]  26112
#define OFF_PI   (OFF_PD + (SEGS - 1) * BLKQ * K17 * 4) // u16   [3][BLKQ][K17]  13056
#define OFF_AMD  (OFF_PI + (SEGS - 1) * BLKQ * K17 * 2) // float [SEGS*BLKQ]      2048
#define OFF_AMI  (OFF_AMD + SEGS * BLKQ * 4)            // int   [SEGS*BLKQ]      2048
#define OFF_RS   (OFF_AMI + SEGS * BLKQ * 4)            // float [SEGS*BLKQ]      2048
#define SMEM_TOTAL (OFF_RS + SEGS * BLKQ * 4)           // = 110848 (~108 KB)

__device__ __forceinline__ void insert17(float* bd, int* bi, float d, int i)
{
#pragma unroll
    for (int t = 0; t < K17; ++t) {
        if (d < bd[t]) {
            float td = bd[t]; bd[t] = d; d = td;
            int   ti = bi[t]; bi[t] = i; i = ti;
        }
    }
}

__device__ __forceinline__ void load_tile(float4* tile, const float* pc, int tid)
{
    for (int j = tid; j < NN; j += TPB) {
        float x = pc[3 * j + 0];
        float y = pc[3 * j + 1];
        float z = pc[3 * j + 2];
        tile[j] = make_float4(x, y, z, x * x + y * y + z * z);
    }
}

// Round-3 distance expression, verbatim
__device__ __forceinline__ float dref(float4 p, float ax, float ay, float az, float na)
{
    float dot = fmaf(az, p.z, fmaf(ay, p.y, ax * p.x));
    return fmaf(-2.0f, dot, na + p.w);
}

// Per-segment provable bound: 5th-smallest of 128 stride-8 samples (Round 9
// version — tighter than the Round-11 split variant).
// >=5 candidates/segment are <= s4 => >=20 total <= max_seg(s4) = R => d_(17) <= R.
__device__ __forceinline__ float sample_bound(
    const float4* __restrict__ tile, int segbase,
    float ax, float ay, float az, float na)
{
    float s0 = BIGF, s1 = BIGF, s2 = BIGF, s3 = BIGF, s4 = BIGF;
#pragma unroll 4
    for (int t = 0; t < 128; ++t) {
        float c = dref(tile[segbase + (t << 3)], ax, ay, az, na);
        float m;
        m = fminf(s0, c); c = fmaxf(s0, c); s0 = m;
        m = fminf(s1, c); c = fmaxf(s1, c); s1 = m;
        m = fminf(s2, c); c = fmaxf(s2, c); s2 = m;
        m = fminf(s3, c); c = fmaxf(s3, c); s3 = m;
        m = fminf(s4, c); c = fmaxf(s4, c); s4 = m;
    }
    return s4;
}

// Chunked filtered exact scan (bit-identical selection; see Round 8/9 notes).
// Single deliberate change vs Round 9: unroll 8 (8 independent LDS+dref chains).
template <bool DO_ARGMIN>
__device__ __forceinline__ void scan_seg(
    const float4* __restrict__ tile, int segbase, float R,
    float ax, float ay, float az, float na,
    float bx, float by, float bz, float nb,
    float* bd, int* bi, float* dmin_out, int* jmin_out)
{
    float worst = bd[K17 - 1];
    float lim = fminf(R, worst);
    float dmin = BIGF; int jmin = 0;
    for (int c0 = 0; c0 < SEGN; c0 += CHUNK) {
        float bufd[CCAP];
        int   bufj[CCAP];
        int c = 0;
#pragma unroll 8
        for (int j = c0; j < c0 + CHUNK; ++j) {
            float4 p = tile[segbase + j];
            float d = dref(p, ax, ay, az, na);
            if (DO_ARGMIN) {
                float d2 = dref(p, bx, by, bz, nb);
                if (d2 < dmin) { dmin = d2; jmin = segbase + j; }
            }
            if (d <= lim) {
                if (c < CCAP) { bufd[c] = d; bufj[c] = segbase + j; ++c; }
                else { insert17(bd, bi, d, segbase + j); worst = bd[K17 - 1]; }
            }
        }
        for (int t = 0; t < c; ++t) {
            float d = bufd[t];
            if (d < worst) {
                insert17(bd, bi, d, bufj[t]);
                worst = bd[K17 - 1];
            }
        }
        lim = fminf(R, worst);
    }
    if (DO_ARGMIN) { *dmin_out = dmin; *jmin_out = jmin; }
}

// merge 3 other partial lists into (bd,bi), lists sorted ascending
__device__ __forceinline__ void merge_partials(const float* pd, const unsigned short* pi,
                                               int ql, float* bd, int* bi)
{
    float worst = bd[K17 - 1];
#pragma unroll
    for (int s = 0; s < SEGS - 1; ++s) {
        const float* qd = pd + (s * BLKQ + ql) * K17;
        const unsigned short* qi = pi + (s * BLKQ + ql) * K17;
        for (int t = 0; t < K17; ++t) {
            float d = qd[t];
            if (d >= worst) break;
            insert17(bd, bi, d, (int)qi[t]);
            worst = bd[K17 - 1];
        }
    }
}

__device__ __forceinline__ float kappa_from_topk(const float4* tile,
                                                 float ax, float ay, float az,
                                                 float nx, float ny, float nz,
                                                 const int* bi)
{
    float s = 0.0f;
#pragma unroll
    for (int t = 1; t < K17; ++t) {     // drop entry 0 (self / nearest)
        float4 p = tile[bi[t]];
        float vx = p.x - ax, vy = p.y - ay, vz = p.z - az;
        float nv = sqrtf(vx * vx + vy * vy + vz * vz);
        float inv = 1.0f / (nv + EPSF);
        s += fabsf((vx * nx + vy * ny + vz * nz) * inv);
    }
    return s * (1.0f / KK);
}

__device__ __forceinline__ void publish_partials(float* pd, unsigned short* pi,
                                                 int seg, int ql,
                                                 const float* bd, const int* bi)
{
    float* qd = pd + ((seg - 1) * BLKQ + ql) * K17;
    unsigned short* qi = pi + ((seg - 1) * BLKQ + ql) * K17;
#pragma unroll
    for (int t = 0; t < K17; ++t) { qd[t] = bd[t]; qi[t] = (unsigned short)bi[t]; }
}

// ---------------------------------------------------------------------------
// fused kernel: ori top-17 + adv argmin on the ori tile, then adv top-17.
// Grid = BB * BPB = 148 blocks; block i of a batch covers queries
// [i*NN/BPB, (i+1)*NN/BPB)  (110 or 111 queries; slots up to BLKQ=128).
// ---------------------------------------------------------------------------
__global__ __launch_bounds__(TPB, 1) void kappa_all_kernel(
    const float* __restrict__ ori, const float* __restrict__ adv,
    const float* __restrict__ nrm)
{
    extern __shared__ char smem[];
    float4* tile = (float4*)(smem + OFF_TILE);
    float*  pd   = (float*)(smem + OFF_PD);
    unsigned short* pi = (unsigned short*)(smem + OFF_PI);
    float*  amd  = (float*)(smem + OFF_AMD);
    int*    ami  = (int*)(smem + OFF_AMI);
    float*  rs   = (float*)(smem + OFF_RS);

    const int tid = threadIdx.x;
    const int ql  = tid % BLKQ;
    const int seg = tid / BLKQ;
    const int segbase = seg * SEGN;
    const int b   = blockIdx.x / BPB;
    const int blk = blockIdx.x % BPB;
    const int q0    = (blk * NN) / BPB;
    const int q1    = ((blk + 1) * NN) / BPB;
    const int count = q1 - q0;                 // 110 or 111
    const int q   = q0 + ql;
    const int qe  = (ql < count) ? q : q0;     // clamped for loads
    const bool active = (ql < count);

    const float* pco = ori + (size_t)b * NN * 3;
    const float* pca = adv + (size_t)b * NN * 3;
    const float* nr  = nrm + (size_t)b * NN * 3;

    const float ax = pco[3 * qe + 0];
    const float ay = pco[3 * qe + 1];
    const float az = pco[3 * qe + 2];
    const float na = ax * ax + ay * ay + az * az;
    const float bx = pca[3 * qe + 0];
    const float by = pca[3 * qe + 1];
    const float bz = pca[3 * qe + 2];
    const float nb = bx * bx + by * by + bz * bz;

    // ===================== phase A: ori tile =====================
    load_tile(tile, pco, tid);
    __syncthreads();

    rs[seg * BLKQ + ql] = sample_bound(tile, segbase, ax, ay, az, na);
    __syncthreads();
    float R = fmaxf(fmaxf(rs[0 * BLKQ + ql], rs[1 * BLKQ + ql]),
                    fmaxf(rs[2 * BLKQ + ql], rs[3 * BLKQ + ql]));

    float bd[K17]; int bi[K17];
#pragma unroll
    for (int t = 0; t < K17; ++t) { bd[t] = BIGF; bi[t] = 0; }

    float dmin; int jmin;
    scan_seg<true>(tile, segbase, R, ax, ay, az, na, bx, by, bz, nb,
                   bd, bi, &dmin, &jmin);

    amd[seg * BLKQ + ql] = dmin;
    ami[seg * BLKQ + ql] = jmin;
    if (seg != 0) publish_partials(pd, pi, seg, ql, bd, bi);
    __syncthreads();

    float nx = 0.f, ny = 0.f, nz = 0.f;
    if (seg == 0) {
        merge_partials(pd, pi, ql, bd, bi);
        if (active) {
            float onx = nr[3 * q + 0], ony = nr[3 * q + 1], onz = nr[3 * q + 2];
            g_kappa[0][b][q] = kappa_from_topk(tile, ax, ay, az, onx, ony, onz, bi);
        }
        // gather nearest-ori normal for the adv query (first-min across segs)
        float best = BIGF; int jm = 0;
#pragma unroll
        for (int s = 0; s < SEGS; ++s) {
            float d = amd[s * BLKQ + ql];
            if (d < best) { best = d; jm = ami[s * BLKQ + ql]; }
        }
        nx = nr[3 * jm + 0]; ny = nr[3 * jm + 1]; nz = nr[3 * jm + 2];
    }
    __syncthreads();   // everyone done reading ori tile

    // ===================== phase B: adv tile =====================
    load_tile(tile, pca, tid);
    __syncthreads();

    rs[seg * BLKQ + ql] = sample_bound(tile, segbase, bx, by, bz, nb);
    __syncthreads();
    R = fmaxf(fmaxf(rs[0 * BLKQ + ql], rs[1 * BLKQ + ql]),
              fmaxf(rs[2 * BLKQ + ql], rs[3 * BLKQ + ql]));

#pragma unroll
    for (int t = 0; t < K17; ++t) { bd[t] = BIGF; bi[t] = 0; }

    scan_seg<false>(tile, segbase, R, bx, by, bz, nb, 0.f, 0.f, 0.f, 0.f,
                    bd, bi, &dmin, &jmin);

    if (seg != 0) publish_partials(pd, pi, seg, ql, bd, bi);
    __syncthreads();

    if (seg == 0 && active) {
        merge_partials(pd, pi, ql, bd, bi);
        g_kappa[1][b][q] = kappa_from_topk(tile, bx, by, bz, nx, ny, nz, bi);
    }
}

// ---------------------------------------------------------------------------
// parallel reduce: 8 groups of 128 threads, one per (pass, batch)
// ---------------------------------------------------------------------------
__global__ __launch_bounds__(1024) void reduce_kernel(float* __restrict__ out)
{
    __shared__ double red[1024];
    __shared__ double s_std[8];
    const int tid = threadIdx.x;
    const int g = tid >> 7;
    const int l = tid & 127;
    const int p = g >> 2;
    const int b = g & 3;

    double s = 0.0;
    for (int i = l; i < NN; i += 128) s += (double)g_kappa[p][b][i];
    red[tid] = s;
    __syncthreads();
    for (int st = 64; st > 0; st >>= 1) {
        if (l < st) red[tid] += red[tid + st];
        __syncthreads();
    }
    double mean = red[g << 7] / (double)NN;
    __syncthreads();

    double s2 = 0.0;
    for (int i = l; i < NN; i += 128) {
        double dv = (double)g_kappa[p][b][i] - mean;
        s2 += dv * dv;
    }
    red[tid] = s2;
    __syncthreads();
    for (int st = 64; st > 0; st >>= 1) {
        if (l < st) red[tid] += red[tid + st];
        __syncthreads();
    }
    if (l == 0) s_std[g] = sqrt(red[tid] / (double)(NN - 1));
    __syncthreads();

    if (tid == 0) {
        double acc = 0.0;
        for (int bb = 0; bb < BB; ++bb) acc += fabs(s_std[4 + bb] - s_std[bb]);
        out[0] = (float)(acc / (double)BB);
    }
}

// ---------------------------------------------------------------------------
extern "C" void kernel_launch(void* const* d_in, const int* in_sizes, int n_in,
                              void* d_out, int out_size)
{
    const float* ori = (const float*)d_in[0];
    const float* adv = (const float*)d_in[1];
    const float* nrm = (const float*)d_in[2];
    float* out = (float*)d_out;

    cudaFuncSetAttribute(kappa_all_kernel,
                         cudaFuncAttributeMaxDynamicSharedMemorySize, SMEM_TOTAL);

    kappa_all_kernel<<<BB * BPB, TPB, SMEM_TOTAL>>>(ori, adv, nrm);
    reduce_kernel<<<1, 1024>>>(out);
}